// round 6
// baseline (speedup 1.0000x reference)
#include <cuda_runtime.h>
#include <math.h>
#include <stdint.h>

#define D      512
#define NWAY   5
#define NKPTS  17
#define BM     128
#define BN     256
#define KC     64
#define NCH    8
#define TPB    256
#define HS     260

// ---- smem byte offsets ----
#define SM_A      0          // 2 bufs x 32768
#define SM_B      65536      // 2 bufs x 65536
#define SM_PROTO  196608     // 512*8 f = 16384
#define SM_DIST   212992     // 128*5 f
#define SM_CLS    215552     // 128 f
#define SM_PN     216064     // 8 f
#define SM_TOTAL  216096

// ---- device scratch (allocation-free rule) ----
__device__ float   g_h1[25 * D];
__device__ float   g_proto[NWAY * D];
__device__ uint8_t g_W[2][NCH][65536];  // pre-converted tf32, ldmatrix-block image

// ---------------- helpers ----------------
__device__ __forceinline__ uint32_t smem_u32(const void* p) {
    uint32_t a;
    asm("{ .reg .u64 t; cvta.to.shared.u64 t, %1; cvt.u32.u64 %0, t; }" : "=r"(a) : "l"(p));
    return a;
}
__device__ __forceinline__ uint32_t f2tf32(float f) {
    uint32_t r; asm("cvt.rna.tf32.f32 %0, %1;" : "=r"(r) : "f"(f)); return r;
}
__device__ __forceinline__ void cpa16(void* dst, const void* src) {
    uint32_t d = (uint32_t)__cvta_generic_to_shared(dst);
    asm volatile("cp.async.cg.shared.global [%0], [%1], 16;" :: "r"(d), "l"(src));
}
__device__ __forceinline__ void cp_commit() { asm volatile("cp.async.commit_group;"); }
__device__ __forceinline__ void cp_wait0()  { asm volatile("cp.async.wait_group 0;"); }

__device__ __forceinline__ void ldsm4(uint32_t* r, uint32_t addr) {
    asm volatile("ldmatrix.sync.aligned.m8n8.x4.shared.b16 {%0,%1,%2,%3}, [%4];"
        : "=r"(r[0]), "=r"(r[1]), "=r"(r[2]), "=r"(r[3]) : "r"(addr));
}
__device__ __forceinline__ void mma_tf32(float* d, const uint32_t* a, const uint32_t* b) {
    asm volatile("mma.sync.aligned.m16n8k8.row.col.f32.tf32.tf32.f32 "
        "{%0,%1,%2,%3},{%4,%5,%6,%7},{%8,%9},{%0,%1,%2,%3};"
        : "+f"(d[0]), "+f"(d[1]), "+f"(d[2]), "+f"(d[3])
        : "r"(a[0]), "r"(a[1]), "r"(a[2]), "r"(a[3]), "r"(b[0]), "r"(b[1]));
}

// ---------------- weight pre-convert into ldmatrix-block image ----------------
// Per (y, chunk): blk = ks*64 + noct*2 + khalf, each 128B = 8 n-rows x 16B k-quad.
__global__ void convW(const float* __restrict__ Wo1, const float* __restrict__ Wc1) {
    int k = blockIdx.x;           // 0..511
    int n = threadIdx.x;          // 0..511
    int y = n >> 8, nn = n & 255;
    float v = y ? Wc1[k * BN + nn] : Wo1[k * BN + nn];
    uint32_t t = f2tf32(v);
    int c = k >> 6, kin = k & 63;
    int ks = kin >> 3, kq = kin & 7, kh = kq >> 2, kp = kq & 3;
    int noct = nn >> 3, r = nn & 7;
    uint32_t off = (uint32_t)(ks * 64 + noct * 2 + kh) * 128 + r * 16 + kp * 4;
    *(uint32_t*)&g_W[y][c][off] = t;
}

// ---------------- prototype path ----------------
__global__ void proto1(const float* __restrict__ sf,
                       const float* __restrict__ W1,
                       const float* __restrict__ b1) {
    int s = blockIdx.x;
    int j = blockIdx.y * 64 + (threadIdx.x & 63);
    int kg = threadIdx.x >> 6;
    const float* srow = sf + s * D;
    float acc = 0.f;
    int k0 = kg * 128;
    #pragma unroll 8
    for (int k = k0; k < k0 + 128; k++)
        acc += srow[k] * W1[k * D + j];
    __shared__ float red[TPB];
    red[threadIdx.x] = acc;
    __syncthreads();
    if (threadIdx.x < 64) {
        float v = red[threadIdx.x] + red[threadIdx.x + 64] + red[threadIdx.x + 128]
                + red[threadIdx.x + 192] + b1[j];
        g_h1[s * D + j] = fmaxf(v, 0.f);
    }
}

__global__ void proto2(const float* __restrict__ W2,
                       const float* __restrict__ b2,
                       float* __restrict__ proto_out) {
    int w = blockIdx.x;
    __shared__ float hsum[D];
    int t = threadIdx.x;
    for (int k = t; k < D; k += TPB) {
        float a = 0.f;
        #pragma unroll
        for (int s = 0; s < 5; s++) a += g_h1[(w * 5 + s) * D + k];
        hsum[k] = a;
    }
    __syncthreads();
    int j = blockIdx.y * 64 + (t & 63);
    int kg = t >> 6;
    float acc = 0.f;
    int k0 = kg * 128;
    #pragma unroll 8
    for (int k = k0; k < k0 + 128; k++)
        acc += hsum[k] * W2[k * D + j];
    __shared__ float red[TPB];
    red[t] = acc;
    __syncthreads();
    if (t < 64) {
        float p = (red[t] + red[t + 64] + red[t + 128] + red[t + 192]) * 0.2f + b2[j];
        g_proto[w * D + j] = p;
        #pragma unroll
        for (int kp = 0; kp < NKPTS; kp++)
            proto_out[(size_t)(w * NKPTS + kp) * D + j] = p;
    }
}

// ---------------- main query kernel ----------------
__global__ void __launch_bounds__(TPB, 1)
query_kernel(const float* __restrict__ Q,   const float* __restrict__ IC,
             const float* __restrict__ bo1, const float* __restrict__ Wo2,
             const float* __restrict__ bo2,
             const float* __restrict__ bc1, const float* __restrict__ Wc2,
             const float* __restrict__ bc2,
             const float* __restrict__ temp,
             float* __restrict__ kp_out,  float* __restrict__ conf_out,
             float* __restrict__ dist_out, float* __restrict__ cls_out) {
    extern __shared__ char smem[];
    const uint32_t sb = smem_u32(smem);
    float* sproto = (float*)(smem + SM_PROTO);
    float* sdist  = (float*)(smem + SM_DIST);
    float* scls   = (float*)(smem + SM_CLS);
    float* spn    = (float*)(smem + SM_PN);

    const int tid  = threadIdx.x;
    const int warp = tid >> 5;
    const int lane = tid & 31;
    const int g    = lane >> 2;
    const int qd   = lane & 3;
    const int y    = blockIdx.y;
    const size_t q0 = (size_t)blockIdx.x * BM;

    if (y == 1) {
        for (int i = tid; i < D * 8; i += TPB) {
            int k = i >> 3, w = i & 7;
            sproto[i] = (w < NWAY) ? g_proto[w * D + k] : 0.f;
        }
    }
    __syncthreads();

    // proto norms (y==1)
    if (y == 1 && warp < NWAY) {
        float s = 0.f;
        for (int k = lane; k < D; k += 32) { float v = sproto[k * 8 + warp]; s += v * v; }
        #pragma unroll
        for (int off = 16; off > 0; off >>= 1) s += __shfl_xor_sync(0xffffffffu, s, off);
        if (lane == 0) spn[warp] = sqrtf(s);
    }

    // producer mapping: 2 threads per query row, 32 k each (rows 0..127 = BM)
    const int row = tid >> 1;
    const int hf  = tid & 1;
    const float* qrow = Q + (q0 + row) * D + hf * 32;
    float qq = 0.f, s0 = 0.f, s1 = 0.f, s2 = 0.f, s3 = 0.f, s4 = 0.f;
    float4 v[8];

    auto ldgA = [&](int c) {
        #pragma unroll
        for (int i = 0; i < 8; i++)
            v[i] = *(const float4*)(qrow + (size_t)c * KC + i * 4);
        if (y == 1) {
            const float* pp = sproto + (c * KC + hf * 32) * 8;
            #pragma unroll
            for (int i = 0; i < 8; i++) {
                float f[4] = {v[i].x, v[i].y, v[i].z, v[i].w};
                #pragma unroll
                for (int e = 0; e < 4; e++) {
                    int kk = i * 4 + e;
                    float4 pa = *(const float4*)(pp + kk * 8);
                    float  pb = pp[kk * 8 + 4];
                    qq += f[e] * f[e];
                    s0 += f[e] * pa.x; s1 += f[e] * pa.y; s2 += f[e] * pa.z;
                    s3 += f[e] * pa.w; s4 += f[e] * pb;
                }
            }
        }
    };
    // A image: blk = ks*32 + mtile*4 + khalf*2 + moct, 128B each (8 m-rows x 16B k-quad)
    auto stsA = [&](int buf) {
        char* ab = smem + SM_A + buf * 32768;
        int mtile = row >> 4, moct = (row >> 3) & 1, r = row & 7;
        #pragma unroll
        for (int j = 0; j < 4; j++) {
            int ks = hf * 4 + j;
            float4 fl = v[2 * j], fh = v[2 * j + 1];
            uint4 lo = make_uint4(f2tf32(fl.x), f2tf32(fl.y), f2tf32(fl.z), f2tf32(fl.w));
            uint4 hi = make_uint4(f2tf32(fh.x), f2tf32(fh.y), f2tf32(fh.z), f2tf32(fh.w));
            int base = ks * 32 + mtile * 4 + moct;
            *(uint4*)(ab + (base)     * 128 + r * 16) = lo;   // khalf 0
            *(uint4*)(ab + (base + 2) * 128 + r * 16) = hi;   // khalf 1
        }
    };
    auto ldB = [&](int c, int buf) {
        const uint8_t* src = &g_W[y][c][0];
        char* dst = smem + SM_B + buf * 65536;
        #pragma unroll
        for (int i = 0; i < 16; i++)
            cpa16(dst + tid * 256 + i * 16, src + tid * 256 + i * 16);
        cp_commit();
    };

    // prologue: chunk 0 fully staged
    ldB(0, 0);
    ldgA(0);
    stsA(0);
    cp_wait0();
    __syncthreads();

    float acc[2][16][4];
    #pragma unroll
    for (int mi = 0; mi < 2; mi++)
        #pragma unroll
        for (int ni = 0; ni < 16; ni++)
            #pragma unroll
            for (int i = 0; i < 4; i++) acc[mi][ni][i] = 0.f;

    const int wm = (warp & 3) * 32;
    const int wn = (warp >> 2) * 128;
    const uint32_t a_mt = (uint32_t)((warp & 3) * 2);
    const uint32_t b_blk0 = (uint32_t)(wn >> 2);   // (wn/8)*2 blocks

    #pragma unroll 1
    for (int c = 0; c < NCH; c++) {
        int buf = c & 1;
        if (c < 7) {
            ldgA(c + 1);               // LDG issue; latency hides under compute(c)
            ldB(c + 1, buf ^ 1);       // cp.async; lands during compute(c)
        }

        uint32_t ab = sb + SM_A + buf * 32768;
        uint32_t bbuf = sb + SM_B + buf * 65536;
        #pragma unroll
        for (int ks = 0; ks < 8; ks++) {
            uint32_t a[2][4];
            ldsm4(a[0], ab + (uint32_t)(ks * 32 + (a_mt + 0) * 4) * 128 + lane * 16);
            ldsm4(a[1], ab + (uint32_t)(ks * 32 + (a_mt + 1) * 4) * 128 + lane * 16);
            #pragma unroll
            for (int p = 0; p < 8; p++) {
                uint32_t r[4];
                ldsm4(r, bbuf + (uint32_t)(ks * 64 + b_blk0 + 4 * p) * 128 + lane * 16);
                mma_tf32(acc[0][2 * p],     a[0], r);
                mma_tf32(acc[0][2 * p + 1], a[0], r + 2);
                mma_tf32(acc[1][2 * p],     a[1], r);
                mma_tf32(acc[1][2 * p + 1], a[1], r + 2);
            }
        }
        __syncthreads();               // compute(c) done; A/B(buf^1) free to overwrite
        if (c < 7) {
            stsA(buf ^ 1);             // v ready by now (LDG overlapped compute)
            cp_wait0();                // B(c+1) landed
            __syncthreads();           // stsA + B visible for compute(c+1)
        }
    }

    // distances finalize (y==1): reduce over the 2-lane row pair
    if (y == 1) {
        qq += __shfl_xor_sync(0xffffffffu, qq, 1);
        s0 += __shfl_xor_sync(0xffffffffu, s0, 1);
        s1 += __shfl_xor_sync(0xffffffffu, s1, 1);
        s2 += __shfl_xor_sync(0xffffffffu, s2, 1);
        s3 += __shfl_xor_sync(0xffffffffu, s3, 1);
        s4 += __shfl_xor_sync(0xffffffffu, s4, 1);
        if (hf == 0) {
            const float T = *temp;
            float qn = sqrtf(qq);
            float sv[5] = {s0, s1, s2, s3, s4};
            float best = 3.402823e38f; int bi = 0;
            #pragma unroll
            for (int w = 0; w < NWAY; w++) {
                float denom = fmaxf(qn * spn[w], 1e-8f);
                float dv = (1.0f - sv[w] / denom) / T;
                sdist[row * NWAY + w] = dv;
                if (dv < best) { best = dv; bi = w; }
            }
            scls[row] = (float)bi;
        }
    }

    // store H = relu(acc + bias) into smem base (A+B regions free now)
    {
        const float* bb1 = y ? bc1 : bo1;
        float* Hs = (float*)smem;
        #pragma unroll
        for (int ni = 0; ni < 16; ni++) {
            int colb = wn + ni * 8 + 2 * qd;
            float b0v = bb1[colb], b1v = bb1[colb + 1];
            #pragma unroll
            for (int mi = 0; mi < 2; mi++) {
                int r0 = wm + mi * 16 + g;
                Hs[r0 * HS + colb]           = fmaxf(acc[mi][ni][0] + b0v, 0.f);
                Hs[r0 * HS + colb + 1]       = fmaxf(acc[mi][ni][1] + b1v, 0.f);
                Hs[(r0 + 8) * HS + colb]     = fmaxf(acc[mi][ni][2] + b0v, 0.f);
                Hs[(r0 + 8) * HS + colb + 1] = fmaxf(acc[mi][ni][3] + b1v, 0.f);
            }
        }
    }
    __syncthreads();

    // heads + output writes (warp handles 16 rows)
    const float* Hs = (const float*)smem;
    if (y == 0) {
        for (int rr = 0; rr < 16; rr++) {
            int r = warp * 16 + rr;
            size_t qi = q0 + r;
            float ox = 0.f, oy = 0.f;
            for (int i = lane; i < BN; i += 32) {
                float h = Hs[r * HS + i];
                ox += h * Wo2[2 * i];
                oy += h * Wo2[2 * i + 1];
            }
            #pragma unroll
            for (int off = 16; off > 0; off >>= 1) {
                ox += __shfl_xor_sync(0xffffffffu, ox, off);
                oy += __shfl_xor_sync(0xffffffffu, oy, off);
            }
            float kx = 0.f, ky = 0.f;
            if (lane == 0) {
                ox += bo2[0]; oy += bo2[1];
                kx = IC[qi * 2 + 0] / (1.0f + expf(-ox));
                ky = IC[qi * 2 + 1] / (1.0f + expf(-oy));
            }
            kx = __shfl_sync(0xffffffffu, kx, 0);
            ky = __shfl_sync(0xffffffffu, ky, 0);
            for (int l = lane; l < 2 * NKPTS; l += 32)
                kp_out[qi * (2 * NKPTS) + l] = (l & 1) ? ky : kx;
        }
    } else {
        for (int rr = 0; rr < 16; rr++) {
            int r = warp * 16 + rr;
            size_t qi = q0 + r;
            float cl = 0.f;
            for (int i = lane; i < BN; i += 32)
                cl += Hs[r * HS + i] * Wc2[i];
            #pragma unroll
            for (int off = 16; off > 0; off >>= 1)
                cl += __shfl_xor_sync(0xffffffffu, cl, off);
            float cf = 0.f;
            if (lane == 0)
                cf = 1.0f / (1.0f + expf(-(cl + bc2[0])));
            cf = __shfl_sync(0xffffffffu, cf, 0);
            if (lane < NKPTS)
                conf_out[qi * NKPTS + lane] = cf;
            for (int l = lane; l < NWAY * NKPTS; l += 32)
                dist_out[qi * (NWAY * NKPTS) + l] = sdist[r * NWAY + l / NKPTS];
            if (lane == 0)
                cls_out[qi] = scls[r];
        }
    }
}

extern "C" void kernel_launch(void* const* d_in, const int* in_sizes, int n_in,
                              void* d_out, int out_size) {
    const float* sf   = (const float*)d_in[0];
    const float* Q    = (const float*)d_in[2];
    const float* IC   = (const float*)d_in[3];
    const float* W1   = (const float*)d_in[4];
    const float* b1   = (const float*)d_in[5];
    const float* W2   = (const float*)d_in[6];
    const float* b2   = (const float*)d_in[7];
    const float* Wo1  = (const float*)d_in[8];
    const float* bo1  = (const float*)d_in[9];
    const float* Wo2  = (const float*)d_in[10];
    const float* bo2  = (const float*)d_in[11];
    const float* Wc1  = (const float*)d_in[12];
    const float* bc1  = (const float*)d_in[13];
    const float* Wc2  = (const float*)d_in[14];
    const float* bc2  = (const float*)d_in[15];
    const float* temp = (const float*)d_in[16];

    const int nq = in_sizes[2] / D;

    float* out       = (float*)d_out;
    float* kp_out    = out;
    float* conf_out  = kp_out   + (size_t)nq * 2 * NKPTS;
    float* dist_out  = conf_out + (size_t)nq * NKPTS;
    float* cls_out   = dist_out + (size_t)nq * NWAY * NKPTS;
    float* proto_out = cls_out  + (size_t)nq;

    convW<<<D, D>>>(Wo1, Wc1);
    proto1<<<dim3(25, 8), TPB>>>(sf, W1, b1);
    proto2<<<dim3(NWAY, 8), TPB>>>(W2, b2, proto_out);

    cudaFuncSetAttribute((const void*)query_kernel,
                         cudaFuncAttributeMaxDynamicSharedMemorySize, SM_TOTAL);
    query_kernel<<<dim3(nq / BM, 2), TPB, SM_TOTAL>>>(
        Q, IC, bo1, Wo2, bo2, bc1, Wc2, bc2, temp,
        kp_out, conf_out, dist_out, cls_out);
}

// round 7
// speedup vs baseline: 1.6067x; 1.6067x over previous
#include <cuda_runtime.h>
#include <math.h>
#include <stdint.h>

#define D      512
#define NWAY   5
#define NKPTS  17
#define BM     128
#define BN     256
#define KC     64
#define NCH    8
#define TPB    512
#define PTPB   256
#define AST    68          // A smem stride in floats (conflict-free: 68%32=4)
#define HS     260

// ---- smem byte offsets ----
#define A_BUF_BYTES  34816         // 128*68*4
#define SM_A      0                // 2 bufs
#define SM_B      69632            // 2 x 65536
#define SM_PROTO  200704           // 512*8 f = 16384
#define SM_DIST   217088           // 128*5 f = 2560
#define SM_CLS    219648           // 128 f
#define SM_PN     220160           // 8 f
#define SM_TOTAL  220192

// ---- device scratch (allocation-free rule) ----
__device__ float   g_h1[25 * D];
__device__ float   g_proto[NWAY * D];
__device__ uint8_t g_W[2][NCH][65536];  // tf32, ldmatrix-block image

// ---------------- helpers ----------------
__device__ __forceinline__ uint32_t smem_u32(const void* p) {
    uint32_t a;
    asm("{ .reg .u64 t; cvta.to.shared.u64 t, %1; cvt.u32.u64 %0, t; }" : "=r"(a) : "l"(p));
    return a;
}
__device__ __forceinline__ uint32_t f2tf32(float f) {
    uint32_t r; asm("cvt.rna.tf32.f32 %0, %1;" : "=r"(r) : "f"(f)); return r;
}
__device__ __forceinline__ void cpa16(void* dst, const void* src) {
    uint32_t d = (uint32_t)__cvta_generic_to_shared(dst);
    asm volatile("cp.async.cg.shared.global [%0], [%1], 16;" :: "r"(d), "l"(src));
}
__device__ __forceinline__ void cp_commit() { asm volatile("cp.async.commit_group;"); }
__device__ __forceinline__ void cp_wait0()  { asm volatile("cp.async.wait_group 0;"); }

__device__ __forceinline__ void ldsm4(uint32_t* r, uint32_t addr) {
    asm volatile("ldmatrix.sync.aligned.m8n8.x4.shared.b16 {%0,%1,%2,%3}, [%4];"
        : "=r"(r[0]), "=r"(r[1]), "=r"(r[2]), "=r"(r[3]) : "r"(addr));
}
__device__ __forceinline__ void mma_tf32(float* d, const uint32_t* a, const uint32_t* b) {
    asm volatile("mma.sync.aligned.m16n8k8.row.col.f32.tf32.tf32.f32 "
        "{%0,%1,%2,%3},{%4,%5,%6,%7},{%8,%9},{%0,%1,%2,%3};"
        : "+f"(d[0]), "+f"(d[1]), "+f"(d[2]), "+f"(d[3])
        : "r"(a[0]), "r"(a[1]), "r"(a[2]), "r"(a[3]), "r"(b[0]), "r"(b[1]));
}

// ---------------- weight pre-convert into ldmatrix-block image ----------------
// Per (y, chunk): blk = ks*64 + noct*2 + khalf, 128B each = 8 n-rows x 16B k-quad.
__global__ void convW(const float* __restrict__ Wo1, const float* __restrict__ Wc1) {
    int k = blockIdx.x;           // 0..511
    int n = threadIdx.x;          // 0..511
    int y = n >> 8, nn = n & 255;
    float v = y ? Wc1[k * BN + nn] : Wo1[k * BN + nn];
    uint32_t t = f2tf32(v);
    int c = k >> 6, kin = k & 63;
    int ks = kin >> 3, kq = kin & 7, kh = kq >> 2, kp = kq & 3;
    int noct = nn >> 3, r = nn & 7;
    uint32_t off = (uint32_t)(ks * 64 + noct * 2 + kh) * 128 + r * 16 + kp * 4;
    *(uint32_t*)&g_W[y][c][off] = t;
}

// ---------------- prototype path ----------------
__global__ void proto1(const float* __restrict__ sf,
                       const float* __restrict__ W1,
                       const float* __restrict__ b1) {
    int s = blockIdx.x;
    int j = blockIdx.y * 64 + (threadIdx.x & 63);
    int kg = threadIdx.x >> 6;
    const float* srow = sf + s * D;
    float acc = 0.f;
    int k0 = kg * 128;
    #pragma unroll 8
    for (int k = k0; k < k0 + 128; k++)
        acc += srow[k] * W1[k * D + j];
    __shared__ float red[PTPB];
    red[threadIdx.x] = acc;
    __syncthreads();
    if (threadIdx.x < 64) {
        float v = red[threadIdx.x] + red[threadIdx.x + 64] + red[threadIdx.x + 128]
                + red[threadIdx.x + 192] + b1[j];
        g_h1[s * D + j] = fmaxf(v, 0.f);
    }
}

__global__ void proto2(const float* __restrict__ W2,
                       const float* __restrict__ b2,
                       float* __restrict__ proto_out) {
    int w = blockIdx.x;
    __shared__ float hsum[D];
    int t = threadIdx.x;
    for (int k = t; k < D; k += PTPB) {
        float a = 0.f;
        #pragma unroll
        for (int s = 0; s < 5; s++) a += g_h1[(w * 5 + s) * D + k];
        hsum[k] = a;
    }
    __syncthreads();
    int j = blockIdx.y * 64 + (t & 63);
    int kg = t >> 6;
    float acc = 0.f;
    int k0 = kg * 128;
    #pragma unroll 8
    for (int k = k0; k < k0 + 128; k++)
        acc += hsum[k] * W2[k * D + j];
    __shared__ float red[PTPB];
    red[t] = acc;
    __syncthreads();
    if (t < 64) {
        float p = (red[t] + red[t + 64] + red[t + 128] + red[t + 192]) * 0.2f + b2[j];
        g_proto[w * D + j] = p;
        #pragma unroll
        for (int kp = 0; kp < NKPTS; kp++)
            proto_out[(size_t)(w * NKPTS + kp) * D + j] = p;
    }
}

// ---------------- main query kernel ----------------
__global__ void __launch_bounds__(TPB, 1)
query_kernel(const float* __restrict__ Q,   const float* __restrict__ IC,
             const float* __restrict__ bo1, const float* __restrict__ Wo2,
             const float* __restrict__ bo2,
             const float* __restrict__ bc1, const float* __restrict__ Wc2,
             const float* __restrict__ bc2,
             const float* __restrict__ temp,
             float* __restrict__ kp_out,  float* __restrict__ conf_out,
             float* __restrict__ dist_out, float* __restrict__ cls_out) {
    extern __shared__ char smem[];
    const uint32_t sb = smem_u32(smem);
    float* sproto = (float*)(smem + SM_PROTO);
    float* sdist  = (float*)(smem + SM_DIST);
    float* scls   = (float*)(smem + SM_CLS);
    float* spn    = (float*)(smem + SM_PN);

    const int tid  = threadIdx.x;
    const int warp = tid >> 5;
    const int lane = tid & 31;
    const int g    = lane >> 2;
    const int qd   = lane & 3;
    const int y    = blockIdx.y;
    const size_t q0 = (size_t)blockIdx.x * BM;

    if (y == 1) {
        for (int i = tid; i < D * 8; i += TPB) {
            int k = i >> 3, w = i & 7;
            sproto[i] = (w < NWAY) ? g_proto[w * D + k] : 0.f;
        }
    }
    __syncthreads();

    // proto norms (y==1)
    if (y == 1 && warp < NWAY) {
        float s = 0.f;
        for (int k = lane; k < D; k += 32) { float v = sproto[k * 8 + warp]; s += v * v; }
        #pragma unroll
        for (int off = 16; off > 0; off >>= 1) s += __shfl_xor_sync(0xffffffffu, s, off);
        if (lane == 0) spn[warp] = sqrtf(s);
    }

    // producers: pure cp.async, no register staging
    auto cpA = [&](int c, int buf) {
        char* ad = smem + SM_A + buf * A_BUF_BYTES;
        #pragma unroll
        for (int i = 0; i < 4; i++) {
            int idx = tid + i * TPB;            // 0..2047
            int row = idx >> 4, c4 = idx & 15;
            cpa16(ad + (row * AST + c4 * 4) * 4,
                  Q + (q0 + row) * D + c * KC + c4 * 4);
        }
    };
    auto cpB = [&](int c, int buf) {
        const uint8_t* src = &g_W[y][c][0];
        char* dst = smem + SM_B + buf * 65536;
        #pragma unroll
        for (int i = 0; i < 8; i++)
            cpa16(dst + tid * 128 + i * 16, src + tid * 128 + i * 16);
    };

    // prologue: chunk 0
    cpB(0, 0);
    cpA(0, 0);
    cp_commit();
    cp_wait0();
    __syncthreads();

    float acc[2][8][4];
    #pragma unroll
    for (int mi = 0; mi < 2; mi++)
        #pragma unroll
        for (int ni = 0; ni < 8; ni++)
            #pragma unroll
            for (int i = 0; i < 4; i++) acc[mi][ni][i] = 0.f;

    const int wm = (warp & 3) * 32;            // 4 m-groups
    const int wn = (warp >> 2) * 64;           // 4 n-groups
    const uint32_t b_blk0 = (uint32_t)(wn >> 2);

    // distance accumulators (y==1)
    const int drow = tid >> 2;
    const int dqp  = tid & 3;
    float qq = 0.f, s0 = 0.f, s1 = 0.f, s2 = 0.f, s3 = 0.f, s4 = 0.f;

    #pragma unroll 1
    for (int c = 0; c < NCH; c++) {
        int buf = c & 1;
        if (c < 7) {                           // overlap next-chunk loads with compute
            cpA(c + 1, buf ^ 1);
            cpB(c + 1, buf ^ 1);
            cp_commit();
        }

        const float* aq = (const float*)(smem + SM_A + buf * A_BUF_BYTES);
        uint32_t bbuf = sb + SM_B + buf * 65536;
        #pragma unroll
        for (int ks = 0; ks < 8; ks++) {
            int k0 = ks * 8;
            uint32_t A[2][4];
            #pragma unroll
            for (int mi = 0; mi < 2; mi++) {
                const float* p = aq + (wm + mi * 16 + g) * AST + k0 + qd;
                A[mi][0] = f2tf32(p[0]);
                A[mi][1] = f2tf32(p[8 * AST]);
                A[mi][2] = f2tf32(p[4]);
                A[mi][3] = f2tf32(p[8 * AST + 4]);
            }
            #pragma unroll
            for (int p = 0; p < 4; p++) {
                uint32_t r[4];
                ldsm4(r, bbuf + (uint32_t)(ks * 64 + b_blk0 + 4 * p) * 128 + lane * 16);
                mma_tf32(acc[0][2 * p],     A[0], r);
                mma_tf32(acc[0][2 * p + 1], A[0], r + 2);
                mma_tf32(acc[1][2 * p],     A[1], r);
                mma_tf32(acc[1][2 * p + 1], A[1], r + 2);
            }
        }

        // fused exact-fp32 distances from resident A tile (y==1)
        if (y == 1) {
            const float* qp_ = aq + drow * AST + dqp * 16;
            const float* pp  = sproto + (c * KC + dqp * 16) * 8;
            #pragma unroll
            for (int i = 0; i < 4; i++) {
                float4 v = ((const float4*)qp_)[i];
                float f[4] = {v.x, v.y, v.z, v.w};
                #pragma unroll
                for (int e = 0; e < 4; e++) {
                    int kk = i * 4 + e;
                    float4 pa = *(const float4*)(pp + kk * 8);
                    float  pb = pp[kk * 8 + 4];
                    qq += f[e] * f[e];
                    s0 += f[e] * pa.x; s1 += f[e] * pa.y; s2 += f[e] * pa.z;
                    s3 += f[e] * pa.w; s4 += f[e] * pb;
                }
            }
        }

        if (c < 7) {
            cp_wait0();                        // next chunk landed
            __syncthreads();                   // everyone done with buf; next buf visible
        }
    }
    __syncthreads();                           // compute(7)/dist(7) done before smem reuse

    // distances finalize (y==1): reduce over the 4-lane row group
    if (y == 1) {
        #pragma unroll
        for (int off = 1; off <= 2; off <<= 1) {
            qq += __shfl_xor_sync(0xffffffffu, qq, off);
            s0 += __shfl_xor_sync(0xffffffffu, s0, off);
            s1 += __shfl_xor_sync(0xffffffffu, s1, off);
            s2 += __shfl_xor_sync(0xffffffffu, s2, off);
            s3 += __shfl_xor_sync(0xffffffffu, s3, off);
            s4 += __shfl_xor_sync(0xffffffffu, s4, off);
        }
        if (dqp == 0) {
            const float T = *temp;
            float qn = sqrtf(qq);
            float sv[5] = {s0, s1, s2, s3, s4};
            float best = 3.402823e38f; int bi = 0;
            #pragma unroll
            for (int w = 0; w < NWAY; w++) {
                float denom = fmaxf(qn * spn[w], 1e-8f);
                float dv = (1.0f - sv[w] / denom) / T;
                sdist[drow * NWAY + w] = dv;
                if (dv < best) { best = dv; bi = w; }
            }
            scls[drow] = (float)bi;
        }
    }

    // store H = relu(acc + bias) into smem base
    {
        const float* bb1 = y ? bc1 : bo1;
        float* Hs = (float*)smem;
        #pragma unroll
        for (int ni = 0; ni < 8; ni++) {
            int colb = wn + ni * 8 + 2 * qd;
            float b0v = bb1[colb], b1v = bb1[colb + 1];
            #pragma unroll
            for (int mi = 0; mi < 2; mi++) {
                int r0 = wm + mi * 16 + g;
                Hs[r0 * HS + colb]           = fmaxf(acc[mi][ni][0] + b0v, 0.f);
                Hs[r0 * HS + colb + 1]       = fmaxf(acc[mi][ni][1] + b1v, 0.f);
                Hs[(r0 + 8) * HS + colb]     = fmaxf(acc[mi][ni][2] + b0v, 0.f);
                Hs[(r0 + 8) * HS + colb + 1] = fmaxf(acc[mi][ni][3] + b1v, 0.f);
            }
        }
    }
    __syncthreads();

    // heads + output writes (warp handles 8 rows)
    const float* Hs = (const float*)smem;
    if (y == 0) {
        for (int rr = 0; rr < 8; rr++) {
            int r = warp * 8 + rr;
            size_t qi = q0 + r;
            float ox = 0.f, oy = 0.f;
            for (int i = lane; i < BN; i += 32) {
                float h = Hs[r * HS + i];
                ox += h * Wo2[2 * i];
                oy += h * Wo2[2 * i + 1];
            }
            #pragma unroll
            for (int off = 16; off > 0; off >>= 1) {
                ox += __shfl_xor_sync(0xffffffffu, ox, off);
                oy += __shfl_xor_sync(0xffffffffu, oy, off);
            }
            float kx = 0.f, ky = 0.f;
            if (lane == 0) {
                ox += bo2[0]; oy += bo2[1];
                kx = IC[qi * 2 + 0] / (1.0f + expf(-ox));
                ky = IC[qi * 2 + 1] / (1.0f + expf(-oy));
            }
            kx = __shfl_sync(0xffffffffu, kx, 0);
            ky = __shfl_sync(0xffffffffu, ky, 0);
            for (int l = lane; l < 2 * NKPTS; l += 32)
                kp_out[qi * (2 * NKPTS) + l] = (l & 1) ? ky : kx;
        }
    } else {
        for (int rr = 0; rr < 8; rr++) {
            int r = warp * 8 + rr;
            size_t qi = q0 + r;
            float cl = 0.f;
            for (int i = lane; i < BN; i += 32)
                cl += Hs[r * HS + i] * Wc2[i];
            #pragma unroll
            for (int off = 16; off > 0; off >>= 1)
                cl += __shfl_xor_sync(0xffffffffu, cl, off);
            float cf = 0.f;
            if (lane == 0)
                cf = 1.0f / (1.0f + expf(-(cl + bc2[0])));
            cf = __shfl_sync(0xffffffffu, cf, 0);
            if (lane < NKPTS)
                conf_out[qi * NKPTS + lane] = cf;
            for (int l = lane; l < NWAY * NKPTS; l += 32)
                dist_out[qi * (NWAY * NKPTS) + l] = sdist[r * NWAY + l / NKPTS];
            if (lane == 0)
                cls_out[qi] = scls[r];
        }
    }
}

extern "C" void kernel_launch(void* const* d_in, const int* in_sizes, int n_in,
                              void* d_out, int out_size) {
    const float* sf   = (const float*)d_in[0];
    const float* Q    = (const float*)d_in[2];
    const float* IC   = (const float*)d_in[3];
    const float* W1   = (const float*)d_in[4];
    const float* b1   = (const float*)d_in[5];
    const float* W2   = (const float*)d_in[6];
    const float* b2   = (const float*)d_in[7];
    const float* Wo1  = (const float*)d_in[8];
    const float* bo1  = (const float*)d_in[9];
    const float* Wo2  = (const float*)d_in[10];
    const float* bo2  = (const float*)d_in[11];
    const float* Wc1  = (const float*)d_in[12];
    const float* bc1  = (const float*)d_in[13];
    const float* Wc2  = (const float*)d_in[14];
    const float* bc2  = (const float*)d_in[15];
    const float* temp = (const float*)d_in[16];

    const int nq = in_sizes[2] / D;

    float* out       = (float*)d_out;
    float* kp_out    = out;
    float* conf_out  = kp_out   + (size_t)nq * 2 * NKPTS;
    float* dist_out  = conf_out + (size_t)nq * NKPTS;
    float* cls_out   = dist_out + (size_t)nq * NWAY * NKPTS;
    float* proto_out = cls_out  + (size_t)nq;

    convW<<<D, D>>>(Wo1, Wc1);
    proto1<<<dim3(25, 8), PTPB>>>(sf, W1, b1);
    proto2<<<dim3(NWAY, 8), PTPB>>>(W2, b2, proto_out);

    cudaFuncSetAttribute((const void*)query_kernel,
                         cudaFuncAttributeMaxDynamicSharedMemorySize, SM_TOTAL);
    query_kernel<<<dim3(nq / BM, 2), TPB, SM_TOTAL>>>(
        Q, IC, bo1, Wo2, bo2, bc1, Wc2, bc2, temp,
        kp_out, conf_out, dist_out, cls_out);
}